// round 7
// baseline (speedup 1.0000x reference)
#include <cuda_runtime.h>
#include <math.h>
#include <stdint.h>

// Problem shape (fixed for NonLocal_2559800508895)
#define BN_   8
#define C_    1024
#define T_    16
#define H_    14
#define W_    14
#define D_    512
#define THW_  (T_*H_*W_)     // 3136
#define HP_   7
#define WP_   7
#define P_    (T_*HP_*WP_)   // 784

// ---------------- scratch (static __device__: allocation-guard safe) ----------
__device__ float g_xp   [BN_ * C_ * P_];         //  25.7 MB pooled x [n][c][p]
__device__ float g_theta[BN_ * D_ * THW_];       //  51.4 MB [n][d][t]
__device__ float g_phi  [BN_ * D_ * P_];         //  12.8 MB [n][d][p]
__device__ float g_g    [BN_ * D_ * P_];         //  12.8 MB [n][d][p]
__device__ float g_log  [(long)BN_ * THW_ * P_]; //  78.7 MB [n][t][p] (attn in-place)
__device__ float g_out  [BN_ * D_ * THW_];       //  51.4 MB [n][d][t]

// ---------------- helpers -----------------------------------------------------
__device__ __forceinline__ void split_tf32(float x, uint32_t& hi, uint32_t& lo)
{
    uint32_t u;
    asm("cvt.rna.tf32.f32 %0, %1;" : "=r"(u) : "f"(x));
    hi = u;
    float l = x - __uint_as_float(u);
    asm("cvt.rna.tf32.f32 %0, %1;" : "=r"(lo) : "f"(l));
}

__device__ __forceinline__ void mma_tf32(float* d,
                                         uint32_t a0, uint32_t a1, uint32_t a2, uint32_t a3,
                                         uint32_t b0, uint32_t b1)
{
    asm("mma.sync.aligned.m16n8k8.row.col.f32.tf32.tf32.f32 "
        "{%0,%1,%2,%3}, {%4,%5,%6,%7}, {%8,%9}, {%0,%1,%2,%3};"
        : "+f"(d[0]), "+f"(d[1]), "+f"(d[2]), "+f"(d[3])
        : "r"(a0), "r"(a1), "r"(a2), "r"(a3), "r"(b0), "r"(b1));
}

__device__ __forceinline__ void cp_async16(uint32_t dst, const void* src, bool pred)
{
    int sz = pred ? 16 : 0;
    asm volatile("cp.async.cg.shared.global [%0], [%1], 16, %2;"
                 :: "r"(dst), "l"(src), "r"(sz));
}

// ---------------- max pool (1,2,2) stride (1,2,2) ----------------------------
__global__ void pool_kernel(const float* __restrict__ x, float* __restrict__ xp)
{
    int idx = blockIdx.x * blockDim.x + threadIdx.x;
    const int total = BN_ * C_ * T_ * HP_ * WP_;
    if (idx >= total) return;
    int j   = idx % WP_;
    int i   = (idx / WP_) % HP_;
    int nct = idx / (HP_ * WP_);
    const float* b = x + (long)nct * (H_ * W_) + (i * 2) * W_ + j * 2;
    xp[idx] = fmaxf(fmaxf(b[0], b[1]), fmaxf(b[W_], b[W_ + 1]));
}

// ---------------- 128x128x16 tf32 (3x-split) 3-stage cp.async GEMM ------------
// C[b] = alpha * opA(A[b]) * opB(B[b])  (+ optional residual/affine epilogue)
//   TRANSA=false: A is M x K row-major (lda = K)   -> smem [m][k], stride 20
//   TRANSA=true : A is K x M row-major (lda = M)   -> smem [k][m], stride 136
//   TRANSB=false: B is K x N row-major (ldb = N)   -> smem [k][n], stride 136
//   TRANSB=true : B is N x K row-major (ldb = K)   -> smem [n][k], stride 20
// Twin mode (Aalt != nullptr): gridDim.y is doubled; blocks with
//   blockIdx.y >= gridDim.y/2 use (Aalt, Calt) instead of (A, Cm). Uniform branch.
// Requires: K%16==0, M%4==0, N%4==0, 16B-aligned rows (true for all calls).
// EPI==0 : C = alpha*acc ; EPI==1 : C = xres + scale[m]*acc + bias[m]
#define STAGE_F 2560                      // floats per stage per operand
#define SMEM_BYTES (3 * STAGE_F * 2 * 4)  // 61440 B dynamic

template<int EPI, bool TRANSA, bool TRANSB>
__global__ void __launch_bounds__(256, 1)
gemm_tc(const float* __restrict__ A, int lda, long strideA,
        const float* __restrict__ B, int ldb, long strideB,
        float* __restrict__ Cm, int ldc, long strideC,
        int M, int N, int K, float alpha,
        const float* __restrict__ xres,
        const float* __restrict__ scale,
        const float* __restrict__ bias,
        const float* __restrict__ Aalt = nullptr,
        float* __restrict__ Calt = nullptr)
{
    extern __shared__ float smem_dyn[];
    float* AsBase = smem_dyn;               // 3 stages x 2560
    float* BsBase = smem_dyn + 3 * STAGE_F; // 3 stages x 2560

    const int tid  = threadIdx.x;
    const int lane = tid & 31;
    const int w    = tid >> 5;        // 0..7
    const int wm   = w >> 2;          // 0..1  -> m offset wm*64
    const int wn   = w & 3;           // 0..3  -> n offset wn*32
    const int g    = lane >> 2;       // 0..7  (mma groupID)
    const int cq   = lane & 3;        // 0..3  (mma threadID-in-group)

    int by = blockIdx.y;
    if (Aalt != nullptr) {            // twin mode: upper half of grid.y -> alt pair
        const int half = gridDim.y >> 1;
        if (by >= half) { A = Aalt; Cm = Calt; by -= half; }
    }
    const int m0 = by * 128;
    const int n0 = blockIdx.x * 128;
    const int b  = blockIdx.z;

    A  += (long)b * strideA;
    B  += (long)b * strideB;
    Cm += (long)b * strideC;

    float acc[4][4][4];
#pragma unroll
    for (int i = 0; i < 4; i++)
#pragma unroll
        for (int j = 0; j < 4; j++)
#pragma unroll
            for (int q = 0; q < 4; q++) acc[i][j][q] = 0.f;

    // ---- async loaders: 512 x 16B chunks per tile, 2 per thread ----
    auto loadA = [&](int kt, int slot) {
        const int k0 = kt << 4;
        float* dst = AsBase + slot * STAGE_F;
#pragma unroll
        for (int h = 0; h < 2; h++) {
            const int c = tid + h * 256;
            if (!TRANSA) {
                const int row = c >> 2;          // 0..127
                const int kc  = (c & 3) * 4;     // 0,4,8,12
                uint32_t d = (uint32_t)__cvta_generic_to_shared(&dst[row * 20 + kc]);
                cp_async16(d, A + (long)(m0 + row) * lda + k0 + kc, (m0 + row) < M);
            } else {
                const int k  = c >> 5;           // 0..15
                const int mc = (c & 31) * 4;     // 0..124
                uint32_t d = (uint32_t)__cvta_generic_to_shared(&dst[k * 136 + mc]);
                cp_async16(d, A + (long)(k0 + k) * lda + m0 + mc, (m0 + mc) < M);
            }
        }
    };
    auto loadB = [&](int kt, int slot) {
        const int k0 = kt << 4;
        float* dst = BsBase + slot * STAGE_F;
#pragma unroll
        for (int h = 0; h < 2; h++) {
            const int c = tid + h * 256;
            if (!TRANSB) {
                const int k  = c >> 5;
                const int nc = (c & 31) * 4;
                uint32_t d = (uint32_t)__cvta_generic_to_shared(&dst[k * 136 + nc]);
                cp_async16(d, B + (long)(k0 + k) * ldb + n0 + nc, (n0 + nc) < N);
            } else {
                const int row = c >> 2;
                const int kc  = (c & 3) * 4;
                uint32_t d = (uint32_t)__cvta_generic_to_shared(&dst[row * 20 + kc]);
                cp_async16(d, B + (long)(n0 + row) * ldb + k0 + kc, (n0 + row) < N);
            }
        }
    };

    const int nk = K >> 4;

    loadA(0, 0); loadB(0, 0);
    asm volatile("cp.async.commit_group;");
    if (nk > 1) {
        loadA(1, 1); loadB(1, 1);
        asm volatile("cp.async.commit_group;");
    }

    for (int kt = 0; kt < nk; kt++) {
        // tile kt must be complete; the younger in-flight group (kt+1) may remain
        if (kt + 1 < nk) asm volatile("cp.async.wait_group 1;");
        else             asm volatile("cp.async.wait_group 0;");
        __syncthreads();
        // prefetch tile kt+2 into slot (kt+2)%3 (== slot consumed at iter kt-1,
        // drained by the barrier above)
        if (kt + 2 < nk) {
            const int s = (kt + 2) % 3;
            loadA(kt + 2, s);
            loadB(kt + 2, s);
            asm volatile("cp.async.commit_group;");
        }

        const float* as = AsBase + (kt % 3) * STAGE_F;
        const float* bs = BsBase + (kt % 3) * STAGE_F;
#pragma unroll
        for (int ks = 0; ks < 16; ks += 8) {
            uint32_t Ah[4][4], Al[4][4];
#pragma unroll
            for (int mf = 0; mf < 4; mf++) {
                const int mo = wm * 64 + mf * 16;
                float r0, r1, r2, r3;
                if (!TRANSA) {
                    r0 = as[(mo + g    ) * 20 + ks + cq    ];
                    r1 = as[(mo + g + 8) * 20 + ks + cq    ];
                    r2 = as[(mo + g    ) * 20 + ks + cq + 4];
                    r3 = as[(mo + g + 8) * 20 + ks + cq + 4];
                } else {
                    r0 = as[(ks + cq    ) * 136 + mo + g    ];
                    r1 = as[(ks + cq    ) * 136 + mo + g + 8];
                    r2 = as[(ks + cq + 4) * 136 + mo + g    ];
                    r3 = as[(ks + cq + 4) * 136 + mo + g + 8];
                }
                split_tf32(r0, Ah[mf][0], Al[mf][0]);
                split_tf32(r1, Ah[mf][1], Al[mf][1]);
                split_tf32(r2, Ah[mf][2], Al[mf][2]);
                split_tf32(r3, Ah[mf][3], Al[mf][3]);
            }
#pragma unroll
            for (int nf = 0; nf < 4; nf++) {
                const int no = wn * 32 + nf * 8;
                float rb0, rb1;
                if (!TRANSB) {
                    rb0 = bs[(ks + cq    ) * 136 + no + g];
                    rb1 = bs[(ks + cq + 4) * 136 + no + g];
                } else {
                    rb0 = bs[(no + g) * 20 + ks + cq    ];
                    rb1 = bs[(no + g) * 20 + ks + cq + 4];
                }
                uint32_t bh0, bl0, bh1, bl1;
                split_tf32(rb0, bh0, bl0);
                split_tf32(rb1, bh1, bl1);
#pragma unroll
                for (int mf = 0; mf < 4; mf++) {
                    mma_tf32(acc[mf][nf], Ah[mf][0], Ah[mf][1], Ah[mf][2], Ah[mf][3], bh0, bh1);
                    mma_tf32(acc[mf][nf], Ah[mf][0], Ah[mf][1], Ah[mf][2], Ah[mf][3], bl0, bl1);
                    mma_tf32(acc[mf][nf], Al[mf][0], Al[mf][1], Al[mf][2], Al[mf][3], bh0, bh1);
                }
            }
        }
    }

    // ---- epilogue ----
#pragma unroll
    for (int mf = 0; mf < 4; mf++) {
#pragma unroll
        for (int half = 0; half < 2; half++) {
            const int gm = m0 + wm * 64 + mf * 16 + g + half * 8;
            if (gm >= M) continue;
            float sc = 1.f, bi = 0.f;
            if (EPI == 1) { sc = scale[gm]; bi = bias[gm]; }
            const long rowoff = (long)gm * ldc;
#pragma unroll
            for (int nf = 0; nf < 4; nf++) {
                const int gn = n0 + wn * 32 + nf * 8 + cq * 2;
                if (gn >= N) continue;
                float2 v;
                v.x = acc[mf][nf][half * 2 + 0];
                v.y = acc[mf][nf][half * 2 + 1];
                if (EPI == 0) {
                    v.x *= alpha; v.y *= alpha;
                } else {
                    const float2 xr = *(const float2*)(xres + (long)b * strideC + rowoff + gn);
                    v.x = xr.x + sc * v.x + bi;
                    v.y = xr.y + sc * v.y + bi;
                }
                *(float2*)(Cm + rowoff + gn) = v;
            }
        }
    }
}

// ---------------- softmax over P, in place (coalesced) ------------------------
__global__ void __launch_bounds__(256)
softmax_ip(float* __restrict__ logits)
{
    const int t   = blockIdx.x;
    const int n   = blockIdx.y;
    const int tid = threadIdx.x;
    float* row = logits + ((long)n * THW_ + t) * P_;

    float v[4];
    int cnt = 0;
    float m = -1e30f;
    for (int p = tid; p < P_; p += 256) {
        v[cnt] = row[p];
        m = fmaxf(m, v[cnt]);
        cnt++;
    }

    __shared__ float sred[8];
#pragma unroll
    for (int o = 16; o > 0; o >>= 1) m = fmaxf(m, __shfl_xor_sync(0xffffffffu, m, o));
    if ((tid & 31) == 0) sred[tid >> 5] = m;
    __syncthreads();
    if (tid < 32) {
        float x = (tid < 8) ? sred[tid] : -1e30f;
#pragma unroll
        for (int o = 4; o > 0; o >>= 1) x = fmaxf(x, __shfl_xor_sync(0xffffffffu, x, o));
        if (tid == 0) sred[0] = x;
    }
    __syncthreads();
    m = sred[0];
    __syncthreads();

    float s = 0.f;
    for (int i = 0; i < cnt; i++) { v[i] = __expf(v[i] - m); s += v[i]; }
#pragma unroll
    for (int o = 16; o > 0; o >>= 1) s += __shfl_xor_sync(0xffffffffu, s, o);
    if ((tid & 31) == 0) sred[tid >> 5] = s;
    __syncthreads();
    if (tid < 32) {
        float x = (tid < 8) ? sred[tid] : 0.f;
#pragma unroll
        for (int o = 4; o > 0; o >>= 1) x += __shfl_xor_sync(0xffffffffu, x, o);
        if (tid == 0) sred[0] = x;
    }
    __syncthreads();
    const float inv = 1.f / sred[0];

    cnt = 0;
    for (int p = tid; p < P_; p += 256) {
        row[p] = v[cnt++] * inv;
    }
}

// ---------------- launch ------------------------------------------------------
extern "C" void kernel_launch(void* const* d_in, const int* in_sizes, int n_in,
                              void* d_out, int out_size)
{
    const float* x       = (const float*)d_in[0];
    const float* w_theta = (const float*)d_in[1];
    const float* w_phi   = (const float*)d_in[2];
    const float* w_g     = (const float*)d_in[3];
    const float* w_out   = (const float*)d_in[4];
    const float* nscale  = (const float*)d_in[5];
    const float* nbias   = (const float*)d_in[6];
    float* y = (float*)d_out;

    float *xp, *theta, *phi, *gg, *lg, *outb;
    cudaGetSymbolAddress((void**)&xp,    g_xp);
    cudaGetSymbolAddress((void**)&theta, g_theta);
    cudaGetSymbolAddress((void**)&phi,   g_phi);
    cudaGetSymbolAddress((void**)&gg,    g_g);
    cudaGetSymbolAddress((void**)&lg,    g_log);
    cudaGetSymbolAddress((void**)&outb,  g_out);

    // raise dynamic smem cap (host-side attribute, capture-legal, idempotent)
    cudaFuncSetAttribute(gemm_tc<0, false, false>,
                         cudaFuncAttributeMaxDynamicSharedMemorySize, SMEM_BYTES);
    cudaFuncSetAttribute(gemm_tc<0, true, false>,
                         cudaFuncAttributeMaxDynamicSharedMemorySize, SMEM_BYTES);
    cudaFuncSetAttribute(gemm_tc<0, false, true>,
                         cudaFuncAttributeMaxDynamicSharedMemorySize, SMEM_BYTES);
    cudaFuncSetAttribute(gemm_tc<1, false, false>,
                         cudaFuncAttributeMaxDynamicSharedMemorySize, SMEM_BYTES);

    // 1) max pool
    {
        int total = BN_ * C_ * P_;
        pool_kernel<<<(total + 255) / 256, 256>>>(x, xp);
    }

    // 2) theta = w_theta(512x1024) @ x[n](1024x3136)
    {
        dim3 grid((THW_ + 127) / 128, (D_ + 127) / 128, BN_);
        gemm_tc<0, false, false><<<grid, 256, SMEM_BYTES>>>(
            w_theta, C_, 0L,
            x, THW_, (long)C_ * THW_,
            theta, THW_, (long)D_ * THW_,
            D_, THW_, C_, 1.0f, nullptr, nullptr, nullptr);
    }
    // 3+4) twin launch: phi = w_phi @ xp[n], g = w_g @ xp[n]  (shared B tiles)
    {
        dim3 grid((P_ + 127) / 128, 2 * ((D_ + 127) / 128), BN_);
        gemm_tc<0, false, false><<<grid, 256, SMEM_BYTES>>>(
            w_phi, C_, 0L,
            xp, P_, (long)C_ * P_,
            phi, P_, (long)D_ * P_,
            D_, P_, C_, 1.0f, nullptr, nullptr, nullptr,
            w_g, gg);
    }
    // 5) logits = theta^T(3136x512) @ phi(512x784) * D^-0.5   (TN GEMM)
    {
        const float alpha = 0.044194173824159216f; // 512^-0.5
        dim3 grid((P_ + 127) / 128, (THW_ + 127) / 128, BN_);
        gemm_tc<0, true, false><<<grid, 256, SMEM_BYTES>>>(
            theta, THW_, (long)D_ * THW_,
            phi, P_, (long)D_ * P_,
            lg, P_, (long)THW_ * P_,
            THW_, P_, D_, alpha, nullptr, nullptr, nullptr);
    }
    // 6) softmax over P, in place (rows stay [t][p], coalesced)
    {
        dim3 grid(THW_, BN_);
        softmax_ip<<<grid, 256>>>(lg);
    }
    // 7) out = g(512x784) @ attn^T  (attn is [THW][P] row-major -> TRANSB)
    {
        dim3 grid((THW_ + 127) / 128, (D_ + 127) / 128, BN_);
        gemm_tc<0, false, true><<<grid, 256, SMEM_BYTES>>>(
            gg, P_, (long)D_ * P_,
            lg, P_, (long)THW_ * P_,
            outb, THW_, (long)D_ * THW_,
            D_, THW_, P_, 1.0f, nullptr, nullptr, nullptr);
    }
    // 8) y = x + scale*(w_out(1024x512) @ out(512x3136)) + bias
    {
        dim3 grid((THW_ + 127) / 128, (C_ + 127) / 128, BN_);
        gemm_tc<1, false, false><<<grid, 256, SMEM_BYTES>>>(
            w_out, D_, 0L,
            outb, THW_, (long)D_ * THW_,
            y, THW_, (long)C_ * THW_,
            C_, THW_, D_, 1.0f, x, nscale, nbias);
    }
}

// round 11
// speedup vs baseline: 1.5167x; 1.5167x over previous
#include <cuda_runtime.h>
#include <math.h>
#include <stdint.h>

// Problem shape (fixed for NonLocal_2559800508895)
#define BN_   8
#define C_    1024
#define T_    16
#define H_    14
#define W_    14
#define D_    512
#define THW_  (T_*H_*W_)     // 3136
#define HP_   7
#define WP_   7
#define P_    (T_*HP_*WP_)   // 784

// ---------------- scratch (static __device__: allocation-guard safe) ----------
__device__ float g_xp   [BN_ * C_ * P_];         //  25.7 MB pooled x [n][c][p]
__device__ float g_theta[BN_ * D_ * THW_];       //  51.4 MB [n][d][t]
__device__ float g_phi  [BN_ * D_ * P_];         //  12.8 MB [n][d][p]
__device__ float g_g    [BN_ * D_ * P_];         //  12.8 MB [n][d][p]
__device__ float g_log  [(long)BN_ * THW_ * P_]; //  78.7 MB [n][t][p] (attn in-place)
__device__ float g_out  [BN_ * D_ * THW_];       //  51.4 MB [n][d][t]

// ---------------- helpers -----------------------------------------------------
// Split (x0,x1) into packed bf16x2 hi and lo parts: x ~= hi + lo elementwise.
// Packing: low 16 bits = x0 (even k), high 16 bits = x1 (odd k).
__device__ __forceinline__ void pack_split_bf16(float x0, float x1,
                                                uint32_t& hi, uint32_t& lo)
{
    uint32_t h;
    asm("cvt.rn.bf16x2.f32 %0, %1, %2;" : "=r"(h) : "f"(x1), "f"(x0));
    float h0 = __uint_as_float(h << 16);
    float h1 = __uint_as_float(h & 0xffff0000u);
    float r0 = x0 - h0;
    float r1 = x1 - h1;
    uint32_t l;
    asm("cvt.rn.bf16x2.f32 %0, %1, %2;" : "=r"(l) : "f"(r1), "f"(r0));
    hi = h; lo = l;
}

__device__ __forceinline__ void mma_bf16(float* d,
                                         uint32_t a0, uint32_t a1, uint32_t a2, uint32_t a3,
                                         uint32_t b0, uint32_t b1)
{
    asm("mma.sync.aligned.m16n8k16.row.col.f32.bf16.bf16.f32 "
        "{%0,%1,%2,%3}, {%4,%5,%6,%7}, {%8,%9}, {%0,%1,%2,%3};"
        : "+f"(d[0]), "+f"(d[1]), "+f"(d[2]), "+f"(d[3])
        : "r"(a0), "r"(a1), "r"(a2), "r"(a3), "r"(b0), "r"(b1));
}

__device__ __forceinline__ void cp_async16(uint32_t dst, const void* src, bool pred)
{
    int sz = pred ? 16 : 0;
    asm volatile("cp.async.cg.shared.global [%0], [%1], 16, %2;"
                 :: "r"(dst), "l"(src), "r"(sz));
}

// ---------------- max pool (1,2,2) stride (1,2,2) ----------------------------
__global__ void pool_kernel(const float* __restrict__ x, float* __restrict__ xp)
{
    int idx = blockIdx.x * blockDim.x + threadIdx.x;
    const int total = BN_ * C_ * T_ * HP_ * WP_;
    if (idx >= total) return;
    int j   = idx % WP_;
    int i   = (idx / WP_) % HP_;
    int nct = idx / (HP_ * WP_);
    const float* b = x + (long)nct * (H_ * W_) + (i * 2) * W_ + j * 2;
    xp[idx] = fmaxf(fmaxf(b[0], b[1]), fmaxf(b[W_], b[W_ + 1]));
}

// ---------------- 128x128x16 bf16 (3x-split) 3-stage cp.async GEMM ------------
// C[b] = alpha * opA(A[b]) * opB(B[b])  (+ optional residual/affine epilogue)
//   TRANSA=false: A is M x K row-major (lda = K)   -> smem [m][k], stride 24
//   TRANSA=true : A is K x M row-major (lda = M)   -> smem [k][m], stride 132
//   TRANSB=false: B is K x N row-major (ldb = N)   -> smem [k][n], stride 132
//   TRANSB=true : B is N x K row-major (ldb = K)   -> smem [n][k], stride 24
// Twin mode (Aalt != nullptr): gridDim.y is doubled; blocks with
//   blockIdx.y >= gridDim.y/2 use (Aalt, Calt) instead of (A, Cm). Uniform branch.
// Requires: K%16==0, M%4==0, N%4==0, 16B-aligned rows (true for all calls).
// EPI==0 : C = alpha*acc ; EPI==1 : C = xres + scale[m]*acc + bias[m]
#define MKSTR 24                          // [m][k]/[n][k] row stride (floats)
#define KSTR  132                         // [k][m]/[k][n] row stride (floats)
#define STAGE_F 3072                      // floats per stage per operand
#define SMEM_BYTES (3 * STAGE_F * 2 * 4)  // 73728 B dynamic

template<int EPI, bool TRANSA, bool TRANSB>
__global__ void __launch_bounds__(256, 1)
gemm_tc(const float* __restrict__ A, int lda, long strideA,
        const float* __restrict__ B, int ldb, long strideB,
        float* __restrict__ Cm, int ldc, long strideC,
        int M, int N, int K, float alpha,
        const float* __restrict__ xres,
        const float* __restrict__ scale,
        const float* __restrict__ bias,
        const float* __restrict__ Aalt = nullptr,
        float* __restrict__ Calt = nullptr)
{
    extern __shared__ float smem_dyn[];
    float* AsBase = smem_dyn;               // 3 stages x 3072
    float* BsBase = smem_dyn + 3 * STAGE_F; // 3 stages x 3072

    const int tid  = threadIdx.x;
    const int lane = tid & 31;
    const int w    = tid >> 5;        // 0..7
    const int wm   = w >> 2;          // 0..1  -> m offset wm*64
    const int wn   = w & 3;           // 0..3  -> n offset wn*32
    const int g    = lane >> 2;       // 0..7  (mma groupID)
    const int cq   = lane & 3;        // 0..3  (mma threadID-in-group)

    int by = blockIdx.y;
    if (Aalt != nullptr) {            // twin mode: upper half of grid.y -> alt pair
        const int half = gridDim.y >> 1;
        if (by >= half) { A = Aalt; Cm = Calt; by -= half; }
    }
    const int m0 = by * 128;
    const int n0 = blockIdx.x * 128;
    const int b  = blockIdx.z;

    A  += (long)b * strideA;
    B  += (long)b * strideB;
    Cm += (long)b * strideC;

    float acc[4][4][4];
#pragma unroll
    for (int i = 0; i < 4; i++)
#pragma unroll
        for (int j = 0; j < 4; j++)
#pragma unroll
            for (int q = 0; q < 4; q++) acc[i][j][q] = 0.f;

    // ---- async loaders: 512 x 16B chunks per tile, 2 per thread ----
    auto loadA = [&](int kt, int slot) {
        const int k0 = kt << 4;
        float* dst = AsBase + slot * STAGE_F;
#pragma unroll
        for (int h = 0; h < 2; h++) {
            const int c = tid + h * 256;
            if (!TRANSA) {
                const int row = c >> 2;          // 0..127
                const int kc  = (c & 3) * 4;     // 0,4,8,12
                uint32_t d = (uint32_t)__cvta_generic_to_shared(&dst[row * MKSTR + kc]);
                cp_async16(d, A + (long)(m0 + row) * lda + k0 + kc, (m0 + row) < M);
            } else {
                const int k  = c >> 5;           // 0..15
                const int mc = (c & 31) * 4;     // 0..124
                uint32_t d = (uint32_t)__cvta_generic_to_shared(&dst[k * KSTR + mc]);
                cp_async16(d, A + (long)(k0 + k) * lda + m0 + mc, (m0 + mc) < M);
            }
        }
    };
    auto loadB = [&](int kt, int slot) {
        const int k0 = kt << 4;
        float* dst = BsBase + slot * STAGE_F;
#pragma unroll
        for (int h = 0; h < 2; h++) {
            const int c = tid + h * 256;
            if (!TRANSB) {
                const int k  = c >> 5;
                const int nc = (c & 31) * 4;
                uint32_t d = (uint32_t)__cvta_generic_to_shared(&dst[k * KSTR + nc]);
                cp_async16(d, B + (long)(k0 + k) * ldb + n0 + nc, (n0 + nc) < N);
            } else {
                const int row = c >> 2;
                const int kc  = (c & 3) * 4;
                uint32_t d = (uint32_t)__cvta_generic_to_shared(&dst[row * MKSTR + kc]);
                cp_async16(d, B + (long)(n0 + row) * ldb + k0 + kc, (n0 + row) < N);
            }
        }
    };

    const int nk = K >> 4;

    loadA(0, 0); loadB(0, 0);
    asm volatile("cp.async.commit_group;");
    if (nk > 1) {
        loadA(1, 1); loadB(1, 1);
        asm volatile("cp.async.commit_group;");
    }

    for (int kt = 0; kt < nk; kt++) {
        // tile kt must be complete; the younger in-flight group (kt+1) may remain
        if (kt + 1 < nk) asm volatile("cp.async.wait_group 1;");
        else             asm volatile("cp.async.wait_group 0;");
        __syncthreads();
        // prefetch tile kt+2 into slot (kt+2)%3 (drained by the barrier above)
        if (kt + 2 < nk) {
            const int s = (kt + 2) % 3;
            loadA(kt + 2, s);
            loadB(kt + 2, s);
            asm volatile("cp.async.commit_group;");
        }

        const float* as = AsBase + (kt % 3) * STAGE_F;
        const float* bs = BsBase + (kt % 3) * STAGE_F;

        // ---- A fragments: one m16n8k16 frag per mf covers the full BK=16 ----
        uint32_t Ah[4][4], Al[4][4];
#pragma unroll
        for (int mf = 0; mf < 4; mf++) {
            const int mo = wm * 64 + mf * 16;
            float v00, v01, v10, v11, v20, v21, v30, v31;
            if (!TRANSA) {
                // k-pairs contiguous: float2 loads (conflict-free per half-warp)
                float2 p0 = *(const float2*)&as[(mo + g    ) * MKSTR + 2 * cq    ];
                float2 p1 = *(const float2*)&as[(mo + g + 8) * MKSTR + 2 * cq    ];
                float2 p2 = *(const float2*)&as[(mo + g    ) * MKSTR + 2 * cq + 8];
                float2 p3 = *(const float2*)&as[(mo + g + 8) * MKSTR + 2 * cq + 8];
                v00 = p0.x; v01 = p0.y; v10 = p1.x; v11 = p1.y;
                v20 = p2.x; v21 = p2.y; v30 = p3.x; v31 = p3.y;
            } else {
                // [k][m] stride 132: banks (8cq+4δ+g) all-unique
                v00 = as[(2 * cq    ) * KSTR + mo + g    ];
                v01 = as[(2 * cq + 1) * KSTR + mo + g    ];
                v10 = as[(2 * cq    ) * KSTR + mo + g + 8];
                v11 = as[(2 * cq + 1) * KSTR + mo + g + 8];
                v20 = as[(2 * cq + 8) * KSTR + mo + g    ];
                v21 = as[(2 * cq + 9) * KSTR + mo + g    ];
                v30 = as[(2 * cq + 8) * KSTR + mo + g + 8];
                v31 = as[(2 * cq + 9) * KSTR + mo + g + 8];
            }
            pack_split_bf16(v00, v01, Ah[mf][0], Al[mf][0]);  // (row g,   k 2cq..)
            pack_split_bf16(v10, v11, Ah[mf][1], Al[mf][1]);  // (row g+8, k 2cq..)
            pack_split_bf16(v20, v21, Ah[mf][2], Al[mf][2]);  // (row g,   k 2cq+8..)
            pack_split_bf16(v30, v31, Ah[mf][3], Al[mf][3]);  // (row g+8, k 2cq+8..)
        }

        // ---- per n-frag: load+split B, run 3-product bf16 mma over m-frags ----
#pragma unroll
        for (int nf = 0; nf < 4; nf++) {
            const int no = wn * 32 + nf * 8;
            float u00, u01, u10, u11;
            if (!TRANSB) {
                u00 = bs[(2 * cq    ) * KSTR + no + g];
                u01 = bs[(2 * cq + 1) * KSTR + no + g];
                u10 = bs[(2 * cq + 8) * KSTR + no + g];
                u11 = bs[(2 * cq + 9) * KSTR + no + g];
            } else {
                float2 q0 = *(const float2*)&bs[(no + g) * MKSTR + 2 * cq    ];
                float2 q1 = *(const float2*)&bs[(no + g) * MKSTR + 2 * cq + 8];
                u00 = q0.x; u01 = q0.y; u10 = q1.x; u11 = q1.y;
            }
            uint32_t bh0, bl0, bh1, bl1;
            pack_split_bf16(u00, u01, bh0, bl0);   // (k 2cq..,   col g)
            pack_split_bf16(u10, u11, bh1, bl1);   // (k 2cq+8.., col g)
#pragma unroll
            for (int mf = 0; mf < 4; mf++) {
                mma_bf16(acc[mf][nf], Ah[mf][0], Ah[mf][1], Ah[mf][2], Ah[mf][3], bh0, bh1);
                mma_bf16(acc[mf][nf], Ah[mf][0], Ah[mf][1], Ah[mf][2], Ah[mf][3], bl0, bl1);
                mma_bf16(acc[mf][nf], Al[mf][0], Al[mf][1], Al[mf][2], Al[mf][3], bh0, bh1);
            }
        }
    }

    // ---- epilogue (accumulator layout identical to m16n8k8) ----
#pragma unroll
    for (int mf = 0; mf < 4; mf++) {
#pragma unroll
        for (int half = 0; half < 2; half++) {
            const int gm = m0 + wm * 64 + mf * 16 + g + half * 8;
            if (gm >= M) continue;
            float sc = 1.f, bi = 0.f;
            if (EPI == 1) { sc = scale[gm]; bi = bias[gm]; }
            const long rowoff = (long)gm * ldc;
#pragma unroll
            for (int nf = 0; nf < 4; nf++) {
                const int gn = n0 + wn * 32 + nf * 8 + cq * 2;
                if (gn >= N) continue;
                float2 v;
                v.x = acc[mf][nf][half * 2 + 0];
                v.y = acc[mf][nf][half * 2 + 1];
                if (EPI == 0) {
                    v.x *= alpha; v.y *= alpha;
                } else {
                    const float2 xr = *(const float2*)(xres + (long)b * strideC + rowoff + gn);
                    v.x = xr.x + sc * v.x + bi;
                    v.y = xr.y + sc * v.y + bi;
                }
                *(float2*)(Cm + rowoff + gn) = v;
            }
        }
    }
}

// ---------------- softmax over P, in place (coalesced) ------------------------
__global__ void __launch_bounds__(256)
softmax_ip(float* __restrict__ logits)
{
    const int t   = blockIdx.x;
    const int n   = blockIdx.y;
    const int tid = threadIdx.x;
    float* row = logits + ((long)n * THW_ + t) * P_;

    float v[4];
    int cnt = 0;
    float m = -1e30f;
    for (int p = tid; p < P_; p += 256) {
        v[cnt] = row[p];
        m = fmaxf(m, v[cnt]);
        cnt++;
    }

    __shared__ float sred[8];
#pragma unroll
    for (int o = 16; o > 0; o >>= 1) m = fmaxf(m, __shfl_xor_sync(0xffffffffu, m, o));
    if ((tid & 31) == 0) sred[tid >> 5] = m;
    __syncthreads();
    if (tid < 32) {
        float x = (tid < 8) ? sred[tid] : -1e30f;
#pragma unroll
        for (int o = 4; o > 0; o >>= 1) x = fmaxf(x, __shfl_xor_sync(0xffffffffu, x, o));
        if (tid == 0) sred[0] = x;
    }
    __syncthreads();
    m = sred[0];
    __syncthreads();

    float s = 0.f;
    for (int i = 0; i < cnt; i++) { v[i] = __expf(v[i] - m); s += v[i]; }
#pragma unroll
    for (int o = 16; o > 0; o >>= 1) s += __shfl_xor_sync(0xffffffffu, s, o);
    if ((tid & 31) == 0) sred[tid >> 5] = s;
    __syncthreads();
    if (tid < 32) {
        float x = (tid < 8) ? sred[tid] : 0.f;
#pragma unroll
        for (int o = 4; o > 0; o >>= 1) x += __shfl_xor_sync(0xffffffffu, x, o);
        if (tid == 0) sred[0] = x;
    }
    __syncthreads();
    const float inv = 1.f / sred[0];

    cnt = 0;
    for (int p = tid; p < P_; p += 256) {
        row[p] = v[cnt++] * inv;
    }
}

// ---------------- launch ------------------------------------------------------
extern "C" void kernel_launch(void* const* d_in, const int* in_sizes, int n_in,
                              void* d_out, int out_size)
{
    const float* x       = (const float*)d_in[0];
    const float* w_theta = (const float*)d_in[1];
    const float* w_phi   = (const float*)d_in[2];
    const float* w_g     = (const float*)d_in[3];
    const float* w_out   = (const float*)d_in[4];
    const float* nscale  = (const float*)d_in[5];
    const float* nbias   = (const float*)d_in[6];
    float* y = (float*)d_out;

    float *xp, *theta, *phi, *gg, *lg, *outb;
    cudaGetSymbolAddress((void**)&xp,    g_xp);
    cudaGetSymbolAddress((void**)&theta, g_theta);
    cudaGetSymbolAddress((void**)&phi,   g_phi);
    cudaGetSymbolAddress((void**)&gg,    g_g);
    cudaGetSymbolAddress((void**)&lg,    g_log);
    cudaGetSymbolAddress((void**)&outb,  g_out);

    // raise dynamic smem cap (host-side attribute, capture-legal, idempotent)
    cudaFuncSetAttribute(gemm_tc<0, false, false>,
                         cudaFuncAttributeMaxDynamicSharedMemorySize, SMEM_BYTES);
    cudaFuncSetAttribute(gemm_tc<0, true, false>,
                         cudaFuncAttributeMaxDynamicSharedMemorySize, SMEM_BYTES);
    cudaFuncSetAttribute(gemm_tc<0, false, true>,
                         cudaFuncAttributeMaxDynamicSharedMemorySize, SMEM_BYTES);
    cudaFuncSetAttribute(gemm_tc<1, false, false>,
                         cudaFuncAttributeMaxDynamicSharedMemorySize, SMEM_BYTES);

    // 1) max pool
    {
        int total = BN_ * C_ * P_;
        pool_kernel<<<(total + 255) / 256, 256>>>(x, xp);
    }

    // 2) theta = w_theta(512x1024) @ x[n](1024x3136)
    {
        dim3 grid((THW_ + 127) / 128, (D_ + 127) / 128, BN_);
        gemm_tc<0, false, false><<<grid, 256, SMEM_BYTES>>>(
            w_theta, C_, 0L,
            x, THW_, (long)C_ * THW_,
            theta, THW_, (long)D_ * THW_,
            D_, THW_, C_, 1.0f, nullptr, nullptr, nullptr);
    }
    // 3+4) twin launch: phi = w_phi @ xp[n], g = w_g @ xp[n]  (shared B tiles)
    {
        dim3 grid((P_ + 127) / 128, 2 * ((D_ + 127) / 128), BN_);
        gemm_tc<0, false, false><<<grid, 256, SMEM_BYTES>>>(
            w_phi, C_, 0L,
            xp, P_, (long)C_ * P_,
            phi, P_, (long)D_ * P_,
            D_, P_, C_, 1.0f, nullptr, nullptr, nullptr,
            w_g, gg);
    }
    // 5) logits = theta^T(3136x512) @ phi(512x784) * D^-0.5   (TN GEMM)
    {
        const float alpha = 0.044194173824159216f; // 512^-0.5
        dim3 grid((P_ + 127) / 128, (THW_ + 127) / 128, BN_);
        gemm_tc<0, true, false><<<grid, 256, SMEM_BYTES>>>(
            theta, THW_, (long)D_ * THW_,
            phi, P_, (long)D_ * P_,
            lg, P_, (long)THW_ * P_,
            THW_, P_, D_, alpha, nullptr, nullptr, nullptr);
    }
    // 6) softmax over P, in place (rows stay [t][p], coalesced)
    {
        dim3 grid(THW_, BN_);
        softmax_ip<<<grid, 256>>>(lg);
    }
    // 7) out = g(512x784) @ attn^T  (attn is [THW][P] row-major -> TRANSB)
    {
        dim3 grid((THW_ + 127) / 128, (D_ + 127) / 128, BN_);
        gemm_tc<0, false, true><<<grid, 256, SMEM_BYTES>>>(
            gg, P_, (long)D_ * P_,
            lg, P_, (long)THW_ * P_,
            outb, THW_, (long)D_ * THW_,
            D_, THW_, P_, 1.0f, nullptr, nullptr, nullptr);
    }
    // 8) y = x + scale*(w_out(1024x512) @ out(512x3136)) + bias
    {
        dim3 grid((THW_ + 127) / 128, (C_ + 127) / 128, BN_);
        gemm_tc<1, false, false><<<grid, 256, SMEM_BYTES>>>(
            w_out, D_, 0L,
            outb, THW_, (long)D_ * THW_,
            y, THW_, (long)C_ * THW_,
            C_, THW_, D_, 1.0f, x, nscale, nbias);
    }
}

// round 14
// speedup vs baseline: 1.9567x; 1.2901x over previous
#include <cuda_runtime.h>
#include <math.h>
#include <stdint.h>

// Problem shape (fixed for NonLocal_2559800508895)
#define BN_   8
#define C_    1024
#define T_    16
#define H_    14
#define W_    14
#define D_    512
#define THW_  (T_*H_*W_)     // 3136
#define HP_   7
#define WP_   7
#define P_    (T_*HP_*WP_)   // 784

// ---------------- scratch (static __device__: allocation-guard safe) ----------
__device__ float g_xp   [BN_ * C_ * P_];         //  25.7 MB pooled x [n][c][p]
__device__ float g_theta[BN_ * D_ * THW_];       //  51.4 MB [n][d][t]
__device__ float g_phi  [BN_ * D_ * P_];         //  12.8 MB [n][d][p]
__device__ float g_g    [BN_ * D_ * P_];         //  12.8 MB [n][d][p]
__device__ float g_log  [(long)BN_ * THW_ * P_]; //  78.7 MB [n][t][p] (attn in-place)
__device__ float g_out  [BN_ * D_ * THW_];       //  51.4 MB [n][d][t]

// ---------------- helpers -----------------------------------------------------
// Split (x0,x1) into packed bf16x2 hi and lo parts: x ~= hi + lo elementwise.
// Packing: low 16 bits = x0 (even k), high 16 bits = x1 (odd k).
__device__ __forceinline__ void pack_split_bf16(float x0, float x1,
                                                uint32_t& hi, uint32_t& lo)
{
    uint32_t h;
    asm("cvt.rn.bf16x2.f32 %0, %1, %2;" : "=r"(h) : "f"(x1), "f"(x0));
    float h0 = __uint_as_float(h << 16);
    float h1 = __uint_as_float(h & 0xffff0000u);
    float r0 = x0 - h0;
    float r1 = x1 - h1;
    uint32_t l;
    asm("cvt.rn.bf16x2.f32 %0, %1, %2;" : "=r"(l) : "f"(r1), "f"(r0));
    hi = h; lo = l;
}

__device__ __forceinline__ void mma_bf16(float* d,
                                         uint32_t a0, uint32_t a1, uint32_t a2, uint32_t a3,
                                         uint32_t b0, uint32_t b1)
{
    asm("mma.sync.aligned.m16n8k16.row.col.f32.bf16.bf16.f32 "
        "{%0,%1,%2,%3}, {%4,%5,%6,%7}, {%8,%9}, {%0,%1,%2,%3};"
        : "+f"(d[0]), "+f"(d[1]), "+f"(d[2]), "+f"(d[3])
        : "r"(a0), "r"(a1), "r"(a2), "r"(a3), "r"(b0), "r"(b1));
}

__device__ __forceinline__ void cp_async16(uint32_t dst, const void* src, bool pred)
{
    int sz = pred ? 16 : 0;
    asm volatile("cp.async.cg.shared.global [%0], [%1], 16, %2;"
                 :: "r"(dst), "l"(src), "r"(sz));
}

// ---------------- max pool (1,2,2) stride (1,2,2) ----------------------------
__global__ void pool_kernel(const float* __restrict__ x, float* __restrict__ xp)
{
    int idx = blockIdx.x * blockDim.x + threadIdx.x;
    const int total = BN_ * C_ * T_ * HP_ * WP_;
    if (idx >= total) return;
    int j   = idx % WP_;
    int i   = (idx / WP_) % HP_;
    int nct = idx / (HP_ * WP_);
    const float* b = x + (long)nct * (H_ * W_) + (i * 2) * W_ + j * 2;
    xp[idx] = fmaxf(fmaxf(b[0], b[1]), fmaxf(b[W_], b[W_ + 1]));
}

// ---------------- 128x128x16 bf16 (3x-split) 3-stage cp.async GEMM ------------
// C[b] = alpha * opA(A[b]) * opB(B[b])  (+ optional residual/affine epilogue)
//   TRANSA=false: A is M x K row-major (lda = K)   -> smem [m][k], stride 24
//   TRANSA=true : A is K x M row-major (lda = M)   -> smem [k][m], stride 132
//   TRANSB=false: B is K x N row-major (ldb = N)   -> smem [k][n], stride 132
//   TRANSB=true : B is N x K row-major (ldb = K)   -> smem [n][k], stride 24
// Twin mode (Aalt != nullptr): gridDim.y is doubled; blocks with
//   blockIdx.y >= gridDim.y/2 use (Aalt, Calt) instead of (A, Cm). Uniform branch.
// Requires: K%16==0, M%4==0, N%4==0, 16B-aligned rows (true for all calls).
// EPI==0 : C = alpha*acc ; EPI==1 : C = xres + scale[m]*acc + bias[m]
#define MKSTR 24                          // [m][k]/[n][k] row stride (floats)
#define KSTR  132                         // [k][m]/[k][n] row stride (floats)
#define STAGE_F 3072                      // floats per stage per operand
#define SMEM_BYTES (3 * STAGE_F * 2 * 4)  // 73728 B dynamic

template<int EPI, bool TRANSA, bool TRANSB>
__global__ void __launch_bounds__(256, 2)
gemm_tc(const float* __restrict__ A, int lda, long strideA,
        const float* __restrict__ B, int ldb, long strideB,
        float* __restrict__ Cm, int ldc, long strideC,
        int M, int N, int K, float alpha,
        const float* __restrict__ xres,
        const float* __restrict__ scale,
        const float* __restrict__ bias,
        const float* __restrict__ Aalt = nullptr,
        float* __restrict__ Calt = nullptr)
{
    extern __shared__ float smem_dyn[];
    float* AsBase = smem_dyn;               // 3 stages x 3072
    float* BsBase = smem_dyn + 3 * STAGE_F; // 3 stages x 3072

    const int tid  = threadIdx.x;
    const int lane = tid & 31;
    const int w    = tid >> 5;        // 0..7
    const int wm   = w >> 2;          // 0..1  -> m offset wm*64
    const int wn   = w & 3;           // 0..3  -> n offset wn*32
    const int g    = lane >> 2;       // 0..7  (mma groupID)
    const int cq   = lane & 3;        // 0..3  (mma threadID-in-group)

    int by = blockIdx.y;
    if (Aalt != nullptr) {            // twin mode: upper half of grid.y -> alt pair
        const int half = gridDim.y >> 1;
        if (by >= half) { A = Aalt; Cm = Calt; by -= half; }
    }
    const int m0 = by * 128;
    const int n0 = blockIdx.x * 128;
    const int b  = blockIdx.z;

    A  += (long)b * strideA;
    B  += (long)b * strideB;
    Cm += (long)b * strideC;

    float acc[4][4][4];
#pragma unroll
    for (int i = 0; i < 4; i++)
#pragma unroll
        for (int j = 0; j < 4; j++)
#pragma unroll
            for (int q = 0; q < 4; q++) acc[i][j][q] = 0.f;

    // ---- async loaders: 512 x 16B chunks per tile, 2 per thread ----
    auto loadA = [&](int kt, int slot) {
        const int k0 = kt << 4;
        float* dst = AsBase + slot * STAGE_F;
#pragma unroll
        for (int h = 0; h < 2; h++) {
            const int c = tid + h * 256;
            if (!TRANSA) {
                const int row = c >> 2;          // 0..127
                const int kc  = (c & 3) * 4;     // 0,4,8,12
                uint32_t d = (uint32_t)__cvta_generic_to_shared(&dst[row * MKSTR + kc]);
                cp_async16(d, A + (long)(m0 + row) * lda + k0 + kc, (m0 + row) < M);
            } else {
                const int k  = c >> 5;           // 0..15
                const int mc = (c & 31) * 4;     // 0..124
                uint32_t d = (uint32_t)__cvta_generic_to_shared(&dst[k * KSTR + mc]);
                cp_async16(d, A + (long)(k0 + k) * lda + m0 + mc, (m0 + mc) < M);
            }
        }
    };
    auto loadB = [&](int kt, int slot) {
        const int k0 = kt << 4;
        float* dst = BsBase + slot * STAGE_F;
#pragma unroll
        for (int h = 0; h < 2; h++) {
            const int c = tid + h * 256;
            if (!TRANSB) {
                const int k  = c >> 5;
                const int nc = (c & 31) * 4;
                uint32_t d = (uint32_t)__cvta_generic_to_shared(&dst[k * KSTR + nc]);
                cp_async16(d, B + (long)(k0 + k) * ldb + n0 + nc, (n0 + nc) < N);
            } else {
                const int row = c >> 2;
                const int kc  = (c & 3) * 4;
                uint32_t d = (uint32_t)__cvta_generic_to_shared(&dst[row * MKSTR + kc]);
                cp_async16(d, B + (long)(n0 + row) * ldb + k0 + kc, (n0 + row) < N);
            }
        }
    };

    const int nk = K >> 4;

    loadA(0, 0); loadB(0, 0);
    asm volatile("cp.async.commit_group;");
    if (nk > 1) {
        loadA(1, 1); loadB(1, 1);
        asm volatile("cp.async.commit_group;");
    }

    for (int kt = 0; kt < nk; kt++) {
        // tile kt must be complete; the younger in-flight group (kt+1) may remain
        if (kt + 1 < nk) asm volatile("cp.async.wait_group 1;");
        else             asm volatile("cp.async.wait_group 0;");
        __syncthreads();
        // prefetch tile kt+2 into slot (kt+2)%3 (drained by the barrier above)
        if (kt + 2 < nk) {
            const int s = (kt + 2) % 3;
            loadA(kt + 2, s);
            loadB(kt + 2, s);
            asm volatile("cp.async.commit_group;");
        }

        const float* as = AsBase + (kt % 3) * STAGE_F;
        const float* bs = BsBase + (kt % 3) * STAGE_F;

        // ---- B fragments for all 4 n-frags first (16 live regs) ----
        uint32_t Bh[4][2], Bl[4][2];
#pragma unroll
        for (int nf = 0; nf < 4; nf++) {
            const int no = wn * 32 + nf * 8;
            float u00, u01, u10, u11;
            if (!TRANSB) {
                u00 = bs[(2 * cq    ) * KSTR + no + g];
                u01 = bs[(2 * cq + 1) * KSTR + no + g];
                u10 = bs[(2 * cq + 8) * KSTR + no + g];
                u11 = bs[(2 * cq + 9) * KSTR + no + g];
            } else {
                float2 q0 = *(const float2*)&bs[(no + g) * MKSTR + 2 * cq    ];
                float2 q1 = *(const float2*)&bs[(no + g) * MKSTR + 2 * cq + 8];
                u00 = q0.x; u01 = q0.y; u10 = q1.x; u11 = q1.y;
            }
            pack_split_bf16(u00, u01, Bh[nf][0], Bl[nf][0]);   // (k 2cq..,   col g)
            pack_split_bf16(u10, u11, Bh[nf][1], Bl[nf][1]);   // (k 2cq+8.., col g)
        }

        // ---- stream A per m-frag (8 transient regs), mma over n-frags ----
#pragma unroll
        for (int mf = 0; mf < 4; mf++) {
            const int mo = wm * 64 + mf * 16;
            float v00, v01, v10, v11, v20, v21, v30, v31;
            if (!TRANSA) {
                // k-pairs contiguous: float2 loads (conflict-free per half-warp)
                float2 p0 = *(const float2*)&as[(mo + g    ) * MKSTR + 2 * cq    ];
                float2 p1 = *(const float2*)&as[(mo + g + 8) * MKSTR + 2 * cq    ];
                float2 p2 = *(const float2*)&as[(mo + g    ) * MKSTR + 2 * cq + 8];
                float2 p3 = *(const float2*)&as[(mo + g + 8) * MKSTR + 2 * cq + 8];
                v00 = p0.x; v01 = p0.y; v10 = p1.x; v11 = p1.y;
                v20 = p2.x; v21 = p2.y; v30 = p3.x; v31 = p3.y;
            } else {
                // [k][m] stride 132: banks (8cq+4δ+g) all-unique
                v00 = as[(2 * cq    ) * KSTR + mo + g    ];
                v01 = as[(2 * cq + 1) * KSTR + mo + g    ];
                v10 = as[(2 * cq    ) * KSTR + mo + g + 8];
                v11 = as[(2 * cq + 1) * KSTR + mo + g + 8];
                v20 = as[(2 * cq + 8) * KSTR + mo + g    ];
                v21 = as[(2 * cq + 9) * KSTR + mo + g    ];
                v30 = as[(2 * cq + 8) * KSTR + mo + g + 8];
                v31 = as[(2 * cq + 9) * KSTR + mo + g + 8];
            }
            uint32_t ah0, al0, ah1, al1, ah2, al2, ah3, al3;
            pack_split_bf16(v00, v01, ah0, al0);  // (row g,   k 2cq..)
            pack_split_bf16(v10, v11, ah1, al1);  // (row g+8, k 2cq..)
            pack_split_bf16(v20, v21, ah2, al2);  // (row g,   k 2cq+8..)
            pack_split_bf16(v30, v31, ah3, al3);  // (row g+8, k 2cq+8..)
#pragma unroll
            for (int nf = 0; nf < 4; nf++) {
                mma_bf16(acc[mf][nf], ah0, ah1, ah2, ah3, Bh[nf][0], Bh[nf][1]);
                mma_bf16(acc[mf][nf], ah0, ah1, ah2, ah3, Bl[nf][0], Bl[nf][1]);
                mma_bf16(acc[mf][nf], al0, al1, al2, al3, Bh[nf][0], Bh[nf][1]);
            }
        }
    }

    // ---- epilogue (accumulator layout identical to m16n8k8) ----
#pragma unroll
    for (int mf = 0; mf < 4; mf++) {
#pragma unroll
        for (int half = 0; half < 2; half++) {
            const int gm = m0 + wm * 64 + mf * 16 + g + half * 8;
            if (gm >= M) continue;
            float sc = 1.f, bi = 0.f;
            if (EPI == 1) { sc = scale[gm]; bi = bias[gm]; }
            const long rowoff = (long)gm * ldc;
#pragma unroll
            for (int nf = 0; nf < 4; nf++) {
                const int gn = n0 + wn * 32 + nf * 8 + cq * 2;
                if (gn >= N) continue;
                float2 v;
                v.x = acc[mf][nf][half * 2 + 0];
                v.y = acc[mf][nf][half * 2 + 1];
                if (EPI == 0) {
                    v.x *= alpha; v.y *= alpha;
                } else {
                    const float2 xr = *(const float2*)(xres + (long)b * strideC + rowoff + gn);
                    v.x = xr.x + sc * v.x + bi;
                    v.y = xr.y + sc * v.y + bi;
                }
                *(float2*)(Cm + rowoff + gn) = v;
            }
        }
    }
}

// ---------------- softmax over P, in place (coalesced) ------------------------
__global__ void __launch_bounds__(256)
softmax_ip(float* __restrict__ logits)
{
    const int t   = blockIdx.x;
    const int n   = blockIdx.y;
    const int tid = threadIdx.x;
    float* row = logits + ((long)n * THW_ + t) * P_;

    float v[4];
    int cnt = 0;
    float m = -1e30f;
    for (int p = tid; p < P_; p += 256) {
        v[cnt] = row[p];
        m = fmaxf(m, v[cnt]);
        cnt++;
    }

    __shared__ float sred[8];
#pragma unroll
    for (int o = 16; o > 0; o >>= 1) m = fmaxf(m, __shfl_xor_sync(0xffffffffu, m, o));
    if ((tid & 31) == 0) sred[tid >> 5] = m;
    __syncthreads();
    if (tid < 32) {
        float x = (tid < 8) ? sred[tid] : -1e30f;
#pragma unroll
        for (int o = 4; o > 0; o >>= 1) x = fmaxf(x, __shfl_xor_sync(0xffffffffu, x, o));
        if (tid == 0) sred[0] = x;
    }
    __syncthreads();
    m = sred[0];
    __syncthreads();

    float s = 0.f;
    for (int i = 0; i < cnt; i++) { v[i] = __expf(v[i] - m); s += v[i]; }
#pragma unroll
    for (int o = 16; o > 0; o >>= 1) s += __shfl_xor_sync(0xffffffffu, s, o);
    if ((tid & 31) == 0) sred[tid >> 5] = s;
    __syncthreads();
    if (tid < 32) {
        float x = (tid < 8) ? sred[tid] : 0.f;
#pragma unroll
        for (int o = 4; o > 0; o >>= 1) x += __shfl_xor_sync(0xffffffffu, x, o);
        if (tid == 0) sred[0] = x;
    }
    __syncthreads();
    const float inv = 1.f / sred[0];

    cnt = 0;
    for (int p = tid; p < P_; p += 256) {
        row[p] = v[cnt++] * inv;
    }
}

// ---------------- launch ------------------------------------------------------
extern "C" void kernel_launch(void* const* d_in, const int* in_sizes, int n_in,
                              void* d_out, int out_size)
{
    const float* x       = (const float*)d_in[0];
    const float* w_theta = (const float*)d_in[1];
    const float* w_phi   = (const float*)d_in[2];
    const float* w_g     = (const float*)d_in[3];
    const float* w_out   = (const float*)d_in[4];
    const float* nscale  = (const float*)d_in[5];
    const float* nbias   = (const float*)d_in[6];
    float* y = (float*)d_out;

    float *xp, *theta, *phi, *gg, *lg, *outb;
    cudaGetSymbolAddress((void**)&xp,    g_xp);
    cudaGetSymbolAddress((void**)&theta, g_theta);
    cudaGetSymbolAddress((void**)&phi,   g_phi);
    cudaGetSymbolAddress((void**)&gg,    g_g);
    cudaGetSymbolAddress((void**)&lg,    g_log);
    cudaGetSymbolAddress((void**)&outb,  g_out);

    // raise dynamic smem cap (host-side attribute, capture-legal, idempotent)
    cudaFuncSetAttribute(gemm_tc<0, false, false>,
                         cudaFuncAttributeMaxDynamicSharedMemorySize, SMEM_BYTES);
    cudaFuncSetAttribute(gemm_tc<0, true, false>,
                         cudaFuncAttributeMaxDynamicSharedMemorySize, SMEM_BYTES);
    cudaFuncSetAttribute(gemm_tc<0, false, true>,
                         cudaFuncAttributeMaxDynamicSharedMemorySize, SMEM_BYTES);
    cudaFuncSetAttribute(gemm_tc<1, false, false>,
                         cudaFuncAttributeMaxDynamicSharedMemorySize, SMEM_BYTES);

    // 1) max pool
    {
        int total = BN_ * C_ * P_;
        pool_kernel<<<(total + 255) / 256, 256>>>(x, xp);
    }

    // 2) theta = w_theta(512x1024) @ x[n](1024x3136)
    {
        dim3 grid((THW_ + 127) / 128, (D_ + 127) / 128, BN_);
        gemm_tc<0, false, false><<<grid, 256, SMEM_BYTES>>>(
            w_theta, C_, 0L,
            x, THW_, (long)C_ * THW_,
            theta, THW_, (long)D_ * THW_,
            D_, THW_, C_, 1.0f, nullptr, nullptr, nullptr);
    }
    // 3+4) twin launch: phi = w_phi @ xp[n], g = w_g @ xp[n]  (shared B tiles)
    {
        dim3 grid((P_ + 127) / 128, 2 * ((D_ + 127) / 128), BN_);
        gemm_tc<0, false, false><<<grid, 256, SMEM_BYTES>>>(
            w_phi, C_, 0L,
            xp, P_, (long)C_ * P_,
            phi, P_, (long)D_ * P_,
            D_, P_, C_, 1.0f, nullptr, nullptr, nullptr,
            w_g, gg);
    }
    // 5) logits = theta^T(3136x512) @ phi(512x784) * D^-0.5   (TN GEMM)
    {
        const float alpha = 0.044194173824159216f; // 512^-0.5
        dim3 grid((P_ + 127) / 128, (THW_ + 127) / 128, BN_);
        gemm_tc<0, true, false><<<grid, 256, SMEM_BYTES>>>(
            theta, THW_, (long)D_ * THW_,
            phi, P_, (long)D_ * P_,
            lg, P_, (long)THW_ * P_,
            THW_, P_, D_, alpha, nullptr, nullptr, nullptr);
    }
    // 6) softmax over P, in place (rows stay [t][p], coalesced)
    {
        dim3 grid(THW_, BN_);
        softmax_ip<<<grid, 256>>>(lg);
    }
    // 7) out = g(512x784) @ attn^T  (attn is [THW][P] row-major -> TRANSB)
    {
        dim3 grid((THW_ + 127) / 128, (D_ + 127) / 128, BN_);
        gemm_tc<0, false, true><<<grid, 256, SMEM_BYTES>>>(
            gg, P_, (long)D_ * P_,
            lg, P_, (long)THW_ * P_,
            outb, THW_, (long)D_ * THW_,
            D_, THW_, P_, 1.0f, nullptr, nullptr, nullptr);
    }
    // 8) y = x + scale*(w_out(1024x512) @ out(512x3136)) + bias
    {
        dim3 grid((THW_ + 127) / 128, (C_ + 127) / 128, BN_);
        gemm_tc<1, false, false><<<grid, 256, SMEM_BYTES>>>(
            w_out, D_, 0L,
            outb, THW_, (long)D_ * THW_,
            y, THW_, (long)C_ * THW_,
            C_, THW_, D_, 1.0f, x, nscale, nbias);
    }
}